// round 4
// baseline (speedup 1.0000x reference)
#include <cuda_runtime.h>

// Conv1d over W (K=3, pad=1) + roll(+1) on H.
// x: (128,128,28,28) f32, w: (32,128,3) f32 -> out: (128,32,28,28) f32.
//
// Round 4 = round 3 kernel with the host-side constant-bank copy FIXED:
// use cudaGetSymbolAddress for both symbols (passing the symbol name as a
// pointer from host code gives the host shadow address -> garbage copy).
//  - weights in __constant__ (LDC = separate constant port, not L1TEX)
//  - x tile row stride 33 + scalar LDS: conflict-free (addr mod 32 distinct)
//  - float4-vectorized x tile load

typedef unsigned long long ull;

__device__ __align__(16) float g_wT[128 * 3 * 32];     // [ci][k][co] scratch
__constant__ __align__(16) float c_wT[128 * 3 * 32];   // same layout, const bank

__device__ __forceinline__ ull fma2(ull a, ull b, ull c) {
    ull d;
    asm("fma.rn.f32x2 %0, %1, %2, %3;" : "=l"(d) : "l"(a), "l"(b), "l"(c));
    return d;
}
__device__ __forceinline__ ull add2(ull a, ull b) {
    ull d;
    asm("add.rn.f32x2 %0, %1, %2;" : "=l"(d) : "l"(a), "l"(b));
    return d;
}
__device__ __forceinline__ ull dup2(float f) {
    ull d;
    unsigned u = __float_as_uint(f);
    asm("mov.b64 %0, {%1, %2};" : "=l"(d) : "r"(u), "r"(u));
    return d;
}
__device__ __forceinline__ void unpack2(ull v, float& lo, float& hi) {
    unsigned a, b;
    asm("mov.b64 {%0, %1}, %2;" : "=r"(a), "=r"(b) : "l"(v));
    lo = __uint_as_float(a);
    hi = __uint_as_float(b);
}

// w global layout [co][ci][k] (co*384 + ci*3 + k) -> wT[(ci*3+k)*32 + co]
__global__ void wT_kernel(const float* __restrict__ w) {
    int i = blockIdx.x * 256 + threadIdx.x;
    if (i < 12288) {
        int co = i / 384;
        int r  = i % 384;
        g_wT[r * 32 + co] = w[i];
    }
}

constexpr int HB = 4;     // h-rows per block
constexpr int NT = 256;   // 8 warps: 4 ci-splits x 2 cout-halves
constexpr int RS = 33;    // smem row stride (floats): conflict-free scalar LDS
constexpr int SMEM_BYTES = 128 * HB * RS * 4;   // 67584

__global__ __launch_bounds__(NT, 2)
void conv_kernel(const float* __restrict__ x, float* __restrict__ out) {
    extern __shared__ __align__(16) float smx[];   // [128*HB][RS]; col0 = x[-1]=0, col29 = x[28]=0
    const int b   = blockIdx.y;
    const int h0  = blockIdx.x * HB;
    const int tid = threadIdx.x;
    const int warp = tid >> 5;
    const int lane = tid & 31;

    // halo zeros
    for (int i = tid; i < 128 * HB; i += NT) {
        smx[i * RS]      = 0.f;
        smx[i * RS + 29] = 0.f;
    }
    // x tile, float4 loads: x[b, ci, h0+hh, 4wq..4wq+3] -> smx[(ci*HB+hh)*RS + 1 + 4wq ..]
    const float4* xg4 = (const float4*)(x + (size_t)b * 128 * 28 * 28);
    for (int i = tid; i < 128 * HB * 7; i += NT) {   // 14 iters
        int ci = i / (HB * 7);
        int r  = i % (HB * 7);
        int hh = r / 7;
        int wq = r % 7;
        float4 v = xg4[(ci * 28 + h0 + hh) * 7 + wq];
        float* d = smx + (ci * HB + hh) * RS + 1 + 4 * wq;
        d[0] = v.x; d[1] = v.y; d[2] = v.z; d[3] = v.w;
    }
    __syncthreads();

    const int s  = warp & 3;          // ci-split: chunk [32*s, 32*s+32)  (warp-uniform)
    const int cg = warp >> 2;         // cout half: [16*cg, 16*cg+16)     (warp-uniform)
    const bool active = lane < 28;
    const int li = active ? lane : 0;
    const int hh = li / 7;
    const int w0 = (li % 7) * 4;

    ull acc[8][4];
#pragma unroll
    for (int j = 0; j < 8; j++)
#pragma unroll
        for (int p = 0; p < 4; p++) acc[j][p] = 0ull;

    const float* xr = smx + ((s * 32) * HB + hh) * RS + w0;   // idx w0 = x[w0-1]
    int woff = (s * 32) * 96 + cg * 16;                       // into c_wT (warp-uniform)

#pragma unroll 2
    for (int ci = 0; ci < 32; ci++) {
        // 6 conflict-free scalar LDS: x[w0-1 .. w0+4]
        ull xd[6];
#pragma unroll
        for (int j = 0; j < 6; j++) xd[j] = dup2(xr[j]);
#pragma unroll
        for (int k = 0; k < 3; k++) {
#pragma unroll
            for (int q = 0; q < 4; q++) {
                // couts 16cg+4q .. +4q+3 as 2 f32x2 pairs, from constant bank
                ulonglong2 wv = *(const ulonglong2*)(c_wT + woff + k * 32 + q * 4);
#pragma unroll
                for (int p = 0; p < 4; p++) {
                    acc[2 * q    ][p] = fma2(wv.x, xd[p + k], acc[2 * q    ][p]);
                    acc[2 * q + 1][p] = fma2(wv.y, xd[p + k], acc[2 * q + 1][p]);
                }
            }
        }
        xr += HB * RS;
        woff += 96;
    }

    // cross-warp reduction of the 4-way ci split through smem (tile is dead now)
    __syncthreads();
    ull* part = (ull*)smx;   // [3][2][28][32] ull = 43008 B <= 66KB
    if (s > 0 && active) {
        ull* dst = part + (((s - 1) * 2 + cg) * 28 + li) * 32;
#pragma unroll
        for (int j = 0; j < 8; j++)
#pragma unroll
            for (int p = 0; p < 4; p++) dst[j * 4 + p] = acc[j][p];
    }
    __syncthreads();

    if (s == 0 && active) {
#pragma unroll
        for (int ps = 0; ps < 3; ps++) {
            const ull* src = part + ((ps * 2 + cg) * 28 + li) * 32;
#pragma unroll
            for (int j = 0; j < 8; j++)
#pragma unroll
                for (int p = 0; p < 4; p++)
                    acc[j][p] = add2(acc[j][p], src[j * 4 + p]);
        }

        int hp = (h0 + hh + 1) % 28;   // roll(+1) along H
#pragma unroll
        for (int j = 0; j < 8; j++) {
            int co = cg * 16 + 2 * j;
            float lo[4], hi[4];
#pragma unroll
            for (int p = 0; p < 4; p++) unpack2(acc[j][p], lo[p], hi[p]);
            float* o0 = out + (((size_t)b * 32 + co) * 28 + hp) * 28 + w0;
            float* o1 = o0 + 784;
            *(float4*)o0 = make_float4(lo[0], lo[1], lo[2], lo[3]);
            *(float4*)o1 = make_float4(hi[0], hi[1], hi[2], hi[3]);
        }
    }
}

extern "C" void kernel_launch(void* const* d_in, const int* in_sizes, int n_in,
                              void* d_out, int out_size) {
    const float* x = (const float*)d_in[0];
    const float* w = (const float*)d_in[1];
    float* out = (float*)d_out;

    cudaFuncSetAttribute(conv_kernel,
                         cudaFuncAttributeMaxDynamicSharedMemorySize, SMEM_BYTES);

    // Resolve REAL device addresses of both symbols (passing the symbol name
    // from host code gives the host-side shadow -> garbage). Then a plain
    // D2D async memcpy, which is graph-capturable and allocation-free.
    void* g_addr = nullptr;
    void* c_addr = nullptr;
    cudaGetSymbolAddress(&g_addr, g_wT);
    cudaGetSymbolAddress(&c_addr, c_wT);

    wT_kernel<<<48, 256>>>(w);
    cudaMemcpyAsync(c_addr, g_addr, 128 * 3 * 32 * sizeof(float),
                    cudaMemcpyDeviceToDevice, 0);
    conv_kernel<<<dim3(7, 128), NT, SMEM_BYTES>>>(x, out);
}

// round 6
// speedup vs baseline: 2.7226x; 2.7226x over previous
#include <cuda_runtime.h>
#include <cstdint>

// Conv1d over W (K=3, pad=1) + roll(+1) on H, as tf32 mma.sync GEMM.
// x: (128,128,28,28) f32, w: (32,128,3) f32 -> out: (128,32,28,28) f32.
//
// tcgen05 is unavailable (harness compiles PTX at compute_103, no 'a'), so use
// classic warp-level mma.sync m16n8k8 tf32 (sm_80+ feature, legal here).
//
// Per block (b, 2 h-rows): D[m=hh*32+mw (56/64 valid), n=cout] =
//   sum_k A[m,k] * B[n,k],  k = kk*128 + ci  (kk-major: a k8 step never
//   crosses a tap boundary),  A[m,k] = x[b,ci,h0+hh,mw+kk-1],
//   B[n,k] = w[n,ci,kk].
// A: compact halo tile in smem (rows ci*2+hh, stride 36, tf32-preconverted),
//    one copy serves all 3 taps. Conflict-free frag LDS: banks 8*tig+gid.
// B: prepared once in global (tf32, [n][k] stride 388), copied to smem.
//    Conflict-free frag LDS: banks 4*gid+tig.
// 8 warps = 2 m32-tiles x 4-way k-split; k-split reduced via smem.

typedef unsigned int u32;

__device__ __align__(16) u32 g_wB[32 * 388];   // tf32 [n][k], stride 388

__device__ __forceinline__ u32 f2tf32(float v) {
    u32 t;
    asm("cvt.rna.tf32.f32 %0, %1;" : "=r"(t) : "f"(v));
    return t;
}

__global__ void wB_kernel(const float* __restrict__ w) {
    int i = blockIdx.x * 256 + threadIdx.x;
    if (i < 32 * 384) {
        int n = i / 384, k = i % 384;
        int ci = k & 127, kk = k >> 7;
        g_wB[n * 388 + k] = f2tf32(w[n * 384 + ci * 3 + kk]);
    }
}

constexpr int RS     = 36;            // A tile row stride (floats)
constexpr int B_OFF  = 256 * RS;      // 9216 u32
constexpr int SMEM_BYTES = (B_OFF + 32 * 388) * 4;   // 86528

__global__ __launch_bounds__(256, 2)
void conv_mma_kernel(const float* __restrict__ x, float* __restrict__ out) {
    extern __shared__ __align__(16) u32 smu[];
    const int tid  = threadIdx.x;
    const int b    = blockIdx.y;
    const int h0   = blockIdx.x * 2;

    // ---- halo zeros: tile col 3 = x[-1], col 32 = x[28] ----
    {
        int r = tid;           // 256 rows, 256 threads
        smu[r * RS + 3]  = 0u;
        smu[r * RS + 32] = 0u;
    }

    // ---- A tile build: x[b,ci,h0+hh,4wq..] -> row ci*2+hh, cols 4+4wq.. (tf32) ----
    const float4* xg4 = (const float4*)x;
#pragma unroll
    for (int t = 0; t < 7; t++) {
        int i  = tid + t * 256;            // 1792 float4
        int ci = i / 14;
        int r  = i % 14;
        int hh = r / 7;
        int wq = r % 7;
        float4 v = xg4[((b * 128 + ci) * 28 + h0 + hh) * 7 + wq];
        uint4 tv = make_uint4(f2tf32(v.x), f2tf32(v.y), f2tf32(v.z), f2tf32(v.w));
        *(uint4*)(smu + (ci * 2 + hh) * RS + 4 + 4 * wq) = tv;
    }

    // ---- B copy: g_wB -> smem (identical layout) ----
    {
        const uint4* src = (const uint4*)g_wB;
        uint4* dst = (uint4*)(smu + B_OFF);
        for (int i = tid; i < (32 * 388) / 4; i += 256) dst[i] = src[i];
    }
    __syncthreads();

    // ---- main loop ----
    const int warp = tid >> 5;
    const int lane = tid & 31;
    const int mi   = warp & 1;        // m32 tile == hh
    const int ks   = warp >> 1;       // k-split 0..3 (96 k each = 12 k8-steps)
    const int gid  = lane >> 2;
    const int tig  = lane & 3;

    float c[2][4][4];
#pragma unroll
    for (int mt = 0; mt < 2; mt++)
#pragma unroll
        for (int nt = 0; nt < 4; nt++)
#pragma unroll
            for (int q = 0; q < 4; q++) c[mt][nt][q] = 0.f;

    const u32* As = smu;
    const u32* Bs = smu + B_OFF;

#pragma unroll 4
    for (int j = 0; j < 12; j++) {
        int k0  = ks * 96 + j * 8;
        int kk  = k0 >> 7;
        int ci0 = k0 & 127;
        // A[m][k] at (ci*2+hh)*RS + mw + kk + 3 ; ci = ci0+tig(+4), mw = mt*16+gid(+8)
        const u32* ap = As + (ci0 + tig) * (2 * RS) + mi * RS + gid + kk + 3;
        const u32* bp = Bs + gid * 388 + k0 + tig;

        u32 a[2][4], bb[4][2];
#pragma unroll
        for (int mt = 0; mt < 2; mt++) {
            const u32* p = ap + mt * 16;
            a[mt][0] = p[0];
            a[mt][1] = p[8];
            a[mt][2] = p[4 * 2 * RS];        // col tig+4 -> ci+4
            a[mt][3] = p[4 * 2 * RS + 8];
        }
#pragma unroll
        for (int nt = 0; nt < 4; nt++) {
            const u32* q = bp + nt * 8 * 388;
            bb[nt][0] = q[0];
            bb[nt][1] = q[4];
        }
#pragma unroll
        for (int mt = 0; mt < 2; mt++)
#pragma unroll
            for (int nt = 0; nt < 4; nt++) {
                asm volatile(
                    "mma.sync.aligned.m16n8k8.row.col.f32.tf32.tf32.f32 "
                    "{%0,%1,%2,%3}, {%4,%5,%6,%7}, {%8,%9}, {%0,%1,%2,%3};"
                    : "+f"(c[mt][nt][0]), "+f"(c[mt][nt][1]),
                      "+f"(c[mt][nt][2]), "+f"(c[mt][nt][3])
                    : "r"(a[mt][0]), "r"(a[mt][1]), "r"(a[mt][2]), "r"(a[mt][3]),
                      "r"(bb[nt][0]), "r"(bb[nt][1]));
            }
    }

    // ---- k-split reduction via smem (reuse A region; 6 x 1056 floats) ----
    __syncthreads();
    float* red = (float*)smu;
    if (ks > 0) {
        float* dst = red + ((ks - 1) * 2 + mi) * 1056;
#pragma unroll
        for (int i = 0; i < 32; i++)
            dst[i * 33 + lane] = c[i >> 4][(i >> 2) & 3][i & 3];
    }
    __syncthreads();

    if (ks == 0) {
#pragma unroll
        for (int ps = 0; ps < 3; ps++) {
            const float* srcp = red + (ps * 2 + mi) * 1056;
#pragma unroll
            for (int i = 0; i < 32; i++)
                c[i >> 4][(i >> 2) & 3][i & 3] += srcp[i * 33 + lane];
        }

        // ---- store with roll(+1) on H ----
        const int hp = (h0 + mi + 1) % 28;
        float* ob = out + (size_t)b * 25088 + hp * 28;
#pragma unroll
        for (int mt = 0; mt < 2; mt++)
#pragma unroll
            for (int nt = 0; nt < 4; nt++)
#pragma unroll
                for (int q = 0; q < 4; q++) {
                    int mw = mt * 16 + gid + ((q >= 2) ? 8 : 0);
                    int co = nt * 8 + 2 * tig + (q & 1);
                    if (mw < 28)
                        ob[(size_t)co * 784 + mw] = c[mt][nt][q];
                }
    }
}

extern "C" void kernel_launch(void* const* d_in, const int* in_sizes, int n_in,
                              void* d_out, int out_size) {
    const float* x = (const float*)d_in[0];
    const float* w = (const float*)d_in[1];
    float* out = (float*)d_out;

    cudaFuncSetAttribute(conv_mma_kernel,
                         cudaFuncAttributeMaxDynamicSharedMemorySize, SMEM_BYTES);

    wB_kernel<<<48, 256>>>(w);
    conv_mma_kernel<<<dim3(14, 128), 256, SMEM_BYTES>>>(x, out);
}